// round 16
// baseline (speedup 1.0000x reference)
#include <cuda_runtime.h>

#define B_ 4
#define H_ 8
#define N_ 256
#define DQ 80
#define DNK 64
#define DEK 16
#define DV 64
#define TQ 16
#define HQ 4              // qq rows per thread-quarter
#define NTHREADS 1024
#define ATT_STRIDE 257

typedef unsigned long long ull;

__device__ __forceinline__ ull pk2(float lo, float hi) {
    ull r; asm("mov.b64 %0, {%1, %2};" : "=l"(r) : "f"(lo), "f"(hi)); return r;
}
__device__ __forceinline__ void upk2(ull p, float& lo, float& hi) {
    asm("mov.b64 {%0, %1}, %2;" : "=f"(lo), "=f"(hi) : "l"(p));
}
__device__ __forceinline__ ull fma2(ull a, ull b, ull c) {
    ull d; asm("fma.rn.f32x2 %0, %1, %2, %3;" : "=l"(d) : "l"(a), "l"(b), "l"(c)); return d;
}

__global__ __launch_bounds__(NTHREADS, 1)
void edge_attn_kernel(const float* __restrict__ q,
                      const float* __restrict__ nk,
                      const float* __restrict__ ek,
                      const float* __restrict__ v,
                      const int*   __restrict__ mask,
                      float* __restrict__ out,       // [B,H,N,DV]
                      float* __restrict__ attn_out)  // [B,H,N,N]
{
    __shared__ float s_qT[DQ * TQ];            // q tile transposed: [d][qq]
    __shared__ float s_attn[TQ * ATT_STRIDE];  // logits -> probs

    const int tid  = threadIdx.x;
    const int k    = tid & 255;      // key
    const int part = tid >> 8;       // 0..3, each owns 4 qq rows
    const int qt   = blockIdx.x;
    const int h    = blockIdx.y;
    const int b    = blockIdx.z;
    const int bh   = b * H_ + h;
    const int q0   = qt * TQ;
    const int qh   = q0 + part * HQ; // first global q row for this quarter

    // ---- issue first ek loads (cold HBM stream) before the sync ----
    const float4* ekp = (const float4*)(ek + (size_t)((bh * N_ + qh) * N_ + k) * DEK);
    float4 e0 = __ldcs(ekp + 0), e1 = __ldcs(ekp + 1),
           e2 = __ldcs(ekp + 2), e3 = __ldcs(ekp + 3);

    // ---- Phase A: q tile transposed into smem ----
    const float* qbase = q + (size_t)(bh * N_ + q0) * DQ;
    for (int i = tid; i < TQ * DQ; i += NTHREADS) {
        int qq = i / DQ;
        int d  = i - qq * DQ;
        s_qT[d * TQ + qq] = qbase[qq * DQ + d];
    }
    __syncthreads();

    float acc[HQ];

    // ---- Phase B1: edge logits for this quarter's 4 rows (prefetch 1 ahead) ----
#define QE(d) s_qT[(DNK + (d)) * TQ + part * HQ + j]
#pragma unroll
    for (int j = 0; j < HQ; j++) {
        float4 f0 = e0, f1 = e1, f2 = e2, f3 = e3;
        if (j < HQ - 1) {
            const float4* e = ekp + (j + 1) * (N_ * DEK / 4);
            e0 = __ldcs(e + 0); e1 = __ldcs(e + 1);
            e2 = __ldcs(e + 2); e3 = __ldcs(e + 3);
        }
        float s0, s1;
        s0  = f0.x * QE(0);
        s0 += f0.y * QE(1);
        s0 += f0.z * QE(2);
        s0 += f0.w * QE(3);
        s0 += f1.x * QE(4);
        s0 += f1.y * QE(5);
        s0 += f1.z * QE(6);
        s0 += f1.w * QE(7);
        s1  = f2.x * QE(8);
        s1 += f2.y * QE(9);
        s1 += f2.z * QE(10);
        s1 += f2.w * QE(11);
        s1 += f3.x * QE(12);
        s1 += f3.y * QE(13);
        s1 += f3.z * QE(14);
        s1 += f3.w * QE(15);
        acc[j] = s0 + s1;
    }
#undef QE

    // pack into f32x2 accumulators (2 packed pairs for 4 rows)
    ull acc2[HQ / 2];
#pragma unroll
    for (int j = 0; j < HQ / 2; j++) acc2[j] = pk2(acc[2 * j], acc[2 * j + 1]);

    // ---- Phase B2: node logits for this quarter's rows, nk streamed from L2 ----
    {
        const float4* nkp = (const float4*)(nk + (size_t)(bh * N_ + k) * DNK);
        // s_qT row d = 4x ulonglong2; this quarter's 4 floats = sq2[d*4 + part]
        const ulonglong2* sq2 = (const ulonglong2*)s_qT;
#pragma unroll
        for (int i = 0; i < 16; i++) {
            float4 nv4 = nkp[i];
#pragma unroll
            for (int c = 0; c < 4; c++) {
                int d = i * 4 + c;
                float nv = (c == 0) ? nv4.x : (c == 1) ? nv4.y : (c == 2) ? nv4.z : nv4.w;
                ull nv2 = pk2(nv, nv);
                ulonglong2 u = sq2[d * 4 + part];
                acc2[0] = fma2(nv2, u.x, acc2[0]);
                acc2[1] = fma2(nv2, u.y, acc2[1]);
            }
        }
#pragma unroll
        for (int j = 0; j < HQ / 2; j++) upk2(acc2[j], acc[2 * j], acc[2 * j + 1]);
    }

    // ---- mask + temperature -> smem logits ----
    {
        const int* mrow = mask + (size_t)(b * N_ + qh) * N_ + k;
#pragma unroll
        for (int j = 0; j < HQ; j++) {
            int m = mrow[j * N_];
            float logit = acc[j] * 0.125f;
            s_attn[(part * HQ + j) * ATT_STRIDE + k] = (m == 0) ? -1000000000.0f : logit;
        }
    }
    __syncthreads();

    // ---- Phase C: softmax, one warp per row (warps 0-15) ----
    const int w    = tid >> 5;
    const int lane = tid & 31;
    if (w < TQ) {
        float* row = s_attn + w * ATT_STRIDE;
        float vals[8];
        float mx = -3.4e38f;
#pragma unroll
        for (int i = 0; i < 8; i++) {
            vals[i] = row[lane + 32 * i];
            mx = fmaxf(mx, vals[i]);
        }
#pragma unroll
        for (int off = 16; off; off >>= 1)
            mx = fmaxf(mx, __shfl_xor_sync(0xffffffffu, mx, off));
        float sum = 0.f;
#pragma unroll
        for (int i = 0; i < 8; i++) {
            float e = __expf(vals[i] - mx);
            vals[i] = e;
            sum += e;
        }
#pragma unroll
        for (int off = 16; off; off >>= 1)
            sum += __shfl_xor_sync(0xffffffffu, sum, off);
        float inv = 1.0f / sum;
        float* attn_g = attn_out + (size_t)(bh * N_ + q0 + w) * N_;
#pragma unroll
        for (int i = 0; i < 8; i++) {
            float p = vals[i] * inv;
            row[lane + 32 * i] = p;
            __stcs(attn_g + lane + 32 * i, p);
        }
    }
    __syncthreads();

    // ---- Phase D: out = attn @ v, 512 threads, thread = (row, 2 dims) ----
    if (tid < 512) {
        const int qq = tid >> 5;           // 0..15
        const int ln = tid & 31;           // 2 dims each: d = ln*2, ln*2+1
        const float* vrow = v + (size_t)(bh * N_) * DV + ln * 2;
        const float* arow = s_attn + qq * ATT_STRIDE;
        ull o0 = 0;
#pragma unroll 4
        for (int kk = 0; kk < N_; kk++) {
            float a = arow[kk];                                    // broadcast LDS
            ull a2 = pk2(a, a);
            ull vv = *(const ull*)(vrow + (size_t)kk * DV);        // LDG.64, L1-resident
            o0 = fma2(a2, vv, o0);
        }
        float2 o;
        upk2(o0, o.x, o.y);
        __stcs((float2*)(out + (size_t)(bh * N_ + q0 + qq) * DV + ln * 2), o);
    }
}

extern "C" void kernel_launch(void* const* d_in, const int* in_sizes, int n_in,
                              void* d_out, int out_size)
{
    const float* q    = (const float*)d_in[0];
    const float* nk   = (const float*)d_in[1];
    const float* ek   = (const float*)d_in[2];
    const float* v    = (const float*)d_in[3];
    const int*   mask = (const int*)d_in[4];

    float* out  = (float*)d_out;                         // [4,8,256,64]
    float* attn = out + (size_t)B_ * H_ * N_ * DV;       // [4,8,256,256]

    dim3 grid(N_ / TQ, H_, B_);
    edge_attn_kernel<<<grid, NTHREADS>>>(q, nk, ek, v, mask, out, attn);
}